// round 12
// baseline (speedup 1.0000x reference)
#include <cuda_runtime.h>
#include <math.h>
#include <stdint.h>

#define NB 4
#define CH 128
#define HH 96
#define WW 96
#define S  48
#define L  2304
#define LLn 5308416   // L*L
#define CHK 36
#define CR  64
#define DCAP 128

// ---- scratch (static device globals; no allocation) ----
__device__ float g_A [(size_t)NB * LLn];
__device__ float g_B2[(size_t)NB * LLn];
__device__ float g_Bs[NB * CH * L];
__device__ float g_Fs[NB * CH * L];
__device__ float g_bcl[NB * HH * WW * CH];
__device__ float g_sq [NB * L];
__device__ float g_invn[NB * L];
__device__ float g_mmv[NB * L];
__device__ float g_pmax[NB * CHK * L];
__device__ float g_psum[NB * CHK * L];
__device__ int   g_ccnt[NB * CHK * L];
__device__ int   g_lidx[(size_t)NB * L * CHK * CR];
__device__ float g_lw  [(size_t)NB * L * CHK * CR];
__device__ int   g_dn  [NB * L];
__device__ int   g_didx[(size_t)NB * L * DCAP];
__device__ float g_dw  [(size_t)NB * L * DCAP];

// ================= prep kernels =================
__global__ void k_sub(const float* __restrict__ b, const float* __restrict__ f) {
    int idx = blockIdx.x * blockDim.x + threadIdx.x;   // NB*CH*L
    int l = idx % L;
    int t = idx / L;
    int c = t % CH;
    int i = t / CH;
    int r = l / S, cc = l % S;
    int src = ((i * CH + c) * HH + 2 * r) * WW + 2 * cc;
    g_Bs[idx] = b[src];
    g_Fs[idx] = f[src];
}

__global__ void k_bcl(const float* __restrict__ b) {
    int idx = blockIdx.x * blockDim.x + threadIdx.x;   // NB*CH*HH*WW
    int x = idx % WW;
    int t = idx / WW;
    int y = t % HH;
    int u = t / HH;
    int c = u % CH;
    int i = u / CH;
    g_bcl[((i * HH + y) * WW + x) * CH + c] = b[idx];
}

__global__ void k_sq(void) {
    int idx = blockIdx.x * blockDim.x + threadIdx.x;   // NB*L
    int i = idx / L, l = idx % L;
    const float* p = g_Bs + (size_t)i * CH * L + l;
    float s = 0.f;
#pragma unroll 8
    for (int c = 0; c < CH; ++c) { float v = p[(size_t)c * L]; s += v * v; }
    g_sq[idx] = s;
}

__global__ void k_norm(void) {
    int idx = blockIdx.x * blockDim.x + threadIdx.x;
    int i = idx / L, l = idx % L;
    int r = l / S, c = l % S;
    float s = 0.f;
    for (int dr = -1; dr <= 1; ++dr)
        for (int dc = -1; dc <= 1; ++dc) {
            int rr = r + dr, cc = c + dc;
            if ((unsigned)rr < S && (unsigned)cc < S) s += g_sq[i * L + rr * S + cc];
        }
    g_invn[idx] = rsqrtf(s + 0.1152f);
}

__global__ void k_mm(const float* __restrict__ mask) {
    int idx = blockIdx.x * blockDim.x + threadIdx.x;
    int i = idx / L, l = idx % L;
    int r = l / S, c = l % S;
    float s = 0.f;
    for (int dr = -1; dr <= 1; ++dr)
        for (int dc = -1; dc <= 1; ++dc) {
            int rr = r + dr, cc = c + dc;
            if ((unsigned)rr < S && (unsigned)cc < S)
                s += mask[i * HH * WW + (2 * rr) * WW + (2 * cc)];
        }
    g_mmv[idx] = (s * (1.0f / 9.0f) == 1.0f) ? 1.f : 0.f;
}

// ================= f32x2 GEMM: G = Bs^T * Fs, [L x L] per sample =================
__global__ __launch_bounds__(256, 2) void k_gemm(void) {
    int i = blockIdx.z;
    const float* A  = g_Bs + (size_t)i * CH * L;   // [K][M]
    const float* Bm = g_Fs + (size_t)i * CH * L;   // [K][N]
    float* Cc = g_A + (size_t)i * LLn;
    int m0 = blockIdx.y * 128, n0 = blockIdx.x * 128;
    __shared__ float sA[16][128], sB[16][128];
    int tid = threadIdx.x;
    int tx = tid & 15, ty = tid >> 4;
    int lr = tid >> 5, lc = (tid & 31) << 2;
    __align__(16) unsigned long long acc2[8][4];
#pragma unroll
    for (int mi = 0; mi < 8; ++mi)
#pragma unroll
        for (int ni = 0; ni < 4; ++ni) acc2[mi][ni] = 0ULL;

    for (int k0 = 0; k0 < CH; k0 += 16) {
#pragma unroll
        for (int sdx = 0; sdx < 2; ++sdx) {
            int kk = lr + sdx * 8;
            *(float4*)&sA[kk][lc] = *(const float4*)&A [(size_t)(k0 + kk) * L + m0 + lc];
            *(float4*)&sB[kk][lc] = *(const float4*)&Bm[(size_t)(k0 + kk) * L + n0 + lc];
        }
        __syncthreads();
#pragma unroll
        for (int kk = 0; kk < 16; ++kk) {
            __align__(16) float av[8], bv[8];
            *(float4*)&av[0] = *(float4*)&sA[kk][ty * 8];
            *(float4*)&av[4] = *(float4*)&sA[kk][ty * 8 + 4];
            *(float4*)&bv[0] = *(float4*)&sB[kk][tx * 8];
            *(float4*)&bv[4] = *(float4*)&sB[kk][tx * 8 + 4];
            const unsigned long long* bp = (const unsigned long long*)bv;
#pragma unroll
            for (int mi = 0; mi < 8; ++mi) {
                unsigned long long a2;
                asm("mov.b64 %0, {%1, %1};" : "=l"(a2) : "f"(av[mi]));
#pragma unroll
                for (int ni = 0; ni < 4; ++ni)
                    asm("fma.rn.f32x2 %0, %1, %2, %0;" : "+l"(acc2[mi][ni]) : "l"(a2), "l"(bp[ni]));
            }
        }
        __syncthreads();
    }
#pragma unroll
    for (int mi = 0; mi < 8; ++mi) {
        float* cp = &Cc[(size_t)(m0 + ty * 8 + mi) * L + n0 + tx * 8];
        const float* ap = (const float*)acc2[mi];
        *(float4*)cp       = *(const float4*)&ap[0];
        *(float4*)(cp + 4) = *(const float4*)&ap[4];
    }
}

// ================= stencil 1: 9-tap masked diagonal band of G, * invn[a] =================
__global__ __launch_bounds__(256) void k_corr(void) {
    int b = blockIdx.x * 256 + threadIdx.x;
    int ch = blockIdx.y, i = blockIdx.z;
    const float* src = g_A + (size_t)i * LLn;
    float* dst = g_B2 + (size_t)i * LLn;
    int r2 = b / S, c2 = b % S;
    for (int rr = 0; rr < 64; ++rr) {
        int a = ch * 64 + rr;
        int r1 = a / S, c1 = a % S;
        float s = 0.f;
#pragma unroll
        for (int dr = -1; dr <= 1; ++dr) {
            if ((unsigned)(r1 + dr) >= S || (unsigned)(r2 + dr) >= S) continue;
#pragma unroll
            for (int dc = -1; dc <= 1; ++dc) {
                if ((unsigned)(c1 + dc) >= S || (unsigned)(c2 + dc) >= S) continue;
                int off = dr * S + dc;
                s += src[(size_t)(a + off) * L + (b + off)];
            }
        }
        dst[(size_t)a * L + b] = s * g_invn[i * L + a];
    }
}

// ===== fuse logit for one (a,b): 9-tap over g_B2 in transposed-flat coords =====
__device__ __forceinline__ float fuse_logit(const float* __restrict__ src,
                                            int a, int aT, int bT, float mmva) {
    float s = 0.f;
#pragma unroll
    for (int d2 = -1; d2 <= 1; ++d2) {
        int ta = aT + d2, tb = bT + d2;
        if ((unsigned)ta >= L || (unsigned)tb >= L) continue;
        int A2 = (ta % S) * S + ta / S;
        int B2 = (tb % S) * S + tb / S;
#pragma unroll
        for (int d1 = -1; d1 <= 1; ++d1) {
            int x = A2 + d1, y = B2 + d1;
            if ((unsigned)x >= L || (unsigned)y >= L) continue;
            s += src[(size_t)x * L + y];
        }
    }
    return s * 10.0f * mmva;
}

// ===== stencil 2: fuse_diag x2 + logit scale -> per-chunk column max ONLY (no write) =====
__global__ __launch_bounds__(256) void k_fuse(void) {
    int b = blockIdx.x * 256 + threadIdx.x;
    int ch = blockIdx.y, i = blockIdx.z;
    const float* src = g_B2 + (size_t)i * LLn;
    int bT = (b % S) * S + b / S;
    float pm = -1e30f;
    for (int rr = 0; rr < CR; ++rr) {
        int a = ch * CR + rr;
        int aT = (a % S) * S + a / S;
        float lg = fuse_logit(src, a, aT, bT, g_mmv[i * L + a]);
        pm = fmaxf(pm, lg);
    }
    g_pmax[(i * CHK + ch) * L + b] = pm;
}

// ===== softmax: global max from pmax, chunk-skip, RECOMPUTE logits for survivors =====
__global__ void k_ext(void) {
    int b = blockIdx.x * 256 + threadIdx.x;
    int ch = blockIdx.y, i = blockIdx.z;
    float pmc = g_pmax[(i * CHK + ch) * L + b];
    float m = -1e30f;
#pragma unroll
    for (int c2 = 0; c2 < CHK; ++c2)
        m = fmaxf(m, g_pmax[(i * CHK + c2) * L + b]);
    if (pmc < m - 25.0f) {
        g_psum[(i * CHK + ch) * L + b] = 0.f;
        g_ccnt[(i * CHK + ch) * L + b] = 0;
        return;
    }
    const float* src = g_B2 + (size_t)i * LLn;
    int bT = (b % S) * S + b / S;
    float s = 0.f;
    int n = 0;
    size_t base = ((size_t)(i * L + b) * CHK + ch) * CR;
    for (int r = 0; r < CR; ++r) {
        int a = ch * CR + r;
        int aT = (a % S) * S + a / S;
        float mmva = g_mmv[i * L + a];
        float lg = fuse_logit(src, a, aT, bT, mmva);
        float d = lg - m;
        if (d > -25.0f) {
            float e = __expf(d);
            s += e;
            if (mmva > 0.5f) {
                g_lidx[base + n] = a;
                g_lw [base + n] = e;
                n++;
            }
        }
    }
    g_psum[(i * CHK + ch) * L + b] = s;
    g_ccnt[(i * CHK + ch) * L + b] = n;
}

// merge chunk lists -> dense list with normalized weights baked in
__global__ void k_comp(void) {
    int idx = blockIdx.x * 256 + threadIdx.x;   // NB*L
    int i = idx / L, b = idx % L;
    float s = 0.f;
#pragma unroll
    for (int ch = 0; ch < CHK; ++ch)
        s += g_psum[(i * CHK + ch) * L + b];
    float inv = 1.0f / s;
    int n = 0;
    size_t sbase = (size_t)(i * L + b) * CHK * CR;
    size_t dbase = (size_t)(i * L + b) * DCAP;
    for (int ch = 0; ch < CHK; ++ch) {
        int c = g_ccnt[(i * CHK + ch) * L + b];
        for (int j = 0; j < c; ++j) {
            if (n < DCAP) {
                g_didx[dbase + n] = g_lidx[sbase + ch * CR + j];
                g_dw [dbase + n] = g_lw [sbase + ch * CR + j] * inv;
            }
            n++;
        }
    }
    g_dn[idx] = n < DCAP ? n : DCAP;
}

// ================= sparse transposed-conv gather =================
__global__ __launch_bounds__(128) void k_out(float* __restrict__ out) {
    int p = blockIdx.x;            // 0..HH*WW-1
    int i = blockIdx.y;
    int c = threadIdx.x;
    int oy = p / WW, ox = p % WW;
    int ua = oy / 2 - 1 + (oy & 1);
    int va = ox / 2 - 1 + (ox & 1);
    float acc = 0.f;
    const float* bcl = g_bcl + (size_t)i * HH * WW * CH;
#pragma unroll
    for (int du = 0; du < 2; ++du) {
        int uu = ua + du;
        if ((unsigned)uu >= S) continue;
#pragma unroll
        for (int dv = 0; dv < 2; ++dv) {
            int vv = va + dv;
            if ((unsigned)vv >= S) continue;
            int bcol = uu * S + vv;
            int n = g_dn[i * L + bcol];
            size_t db = (size_t)(i * L + bcol) * DCAP;
            for (int j = 0; j < n; ++j) {
                int a   = g_didx[db + j];
                float w = g_dw [db + j];
                int r1 = a / S, c1 = a % S;
                int Y = oy + 2 * (r1 - uu);
                int X = ox + 2 * (c1 - vv);
                if ((unsigned)Y < HH && (unsigned)X < WW)
                    acc += w * bcl[((size_t)Y * WW + X) * CH + c];
            }
        }
    }
    out[((size_t)(i * CH + c) * HH + oy) * WW + ox] = acc * 0.25f;
}

extern "C" void kernel_launch(void* const* d_in, const int* in_sizes, int n_in,
                              void* d_out, int out_size) {
    (void)in_sizes; (void)n_in; (void)out_size;
    const float* b    = (const float*)d_in[0];
    const float* f    = (const float*)d_in[1];
    const float* mask = (const float*)d_in[2];
    float* out = (float*)d_out;

    // order chosen so ncu's capture slot lands on a heavy kernel (gemm@4 / corr@6)
    k_sub<<<NB * CH * L / 256, 256>>>(b, f);          // 1
    k_mm  <<<NB * L / 256, 256>>>(mask);              // 2
    k_sq  <<<NB * L / 256, 256>>>();                  // 3
    {
        dim3 gg(L / 128, L / 128, NB);
        k_gemm<<<gg, 256>>>();                        // 4
    }
    k_norm<<<NB * L / 256, 256>>>();                  // 5
    {
        dim3 gs(L / 256, CHK, NB);
        k_corr<<<gs, 256>>>();                        // 6
    }
    k_bcl<<<NB * CH * HH * WW / 256, 256>>>(b);       // 7
    {
        dim3 gs(L / 256, CHK, NB);
        k_fuse<<<gs, 256>>>();                        // 8
        k_ext <<<gs, 256>>>();                        // 9
    }
    k_comp<<<NB * L / 256, 256>>>();                  // 10

    dim3 go(HH * WW, NB);
    k_out<<<go, 128>>>(out);                          // 11
}

// round 13
// speedup vs baseline: 1.2223x; 1.2223x over previous
#include <cuda_runtime.h>
#include <cuda_bf16.h>
#include <math.h>
#include <stdint.h>

#define NB 4
#define CH 128
#define HH 96
#define WW 96
#define S  48
#define L  2304
#define LLn 5308416   // L*L
#define CHK 36
#define CR  64
#define DCAP 128

// ---- scratch (static device globals; no allocation) ----
__device__ float g_A [(size_t)NB * LLn];
__device__ float g_B2[(size_t)NB * LLn];
__device__ float g_Bs[NB * CH * L];
__device__ float g_Fs[NB * CH * L];
__device__ __nv_bfloat16 g_Bh[(size_t)NB * L * CH];
__device__ __nv_bfloat16 g_Bl[(size_t)NB * L * CH];
__device__ __nv_bfloat16 g_Fh[(size_t)NB * L * CH];
__device__ __nv_bfloat16 g_Fl[(size_t)NB * L * CH];
__device__ float g_bcl[NB * HH * WW * CH];
__device__ float g_sq [NB * L];
__device__ float g_invn[NB * L];
__device__ float g_mmv[NB * L];
__device__ float g_pmax[NB * CHK * L];
__device__ float g_psum[NB * CHK * L];
__device__ int   g_ccnt[NB * CHK * L];
__device__ int   g_lidx[(size_t)NB * L * CHK * CR];
__device__ float g_lw  [(size_t)NB * L * CHK * CR];
__device__ int   g_dn  [NB * L];
__device__ int   g_didx[(size_t)NB * L * DCAP];
__device__ float g_dw  [(size_t)NB * L * DCAP];

// ================= prep kernels =================
__global__ void k_sub(const float* __restrict__ b, const float* __restrict__ f) {
    int idx = blockIdx.x * blockDim.x + threadIdx.x;   // NB*CH*L
    int l = idx % L;
    int t = idx / L;
    int c = t % CH;
    int i = t / CH;
    int r = l / S, cc = l % S;
    int src = ((i * CH + c) * HH + 2 * r) * WW + 2 * cc;
    g_Bs[idx] = b[src];
    g_Fs[idx] = f[src];
}

// transpose + bf16 hi/lo split: [i][c][l] f32 -> [i][l][c] bf16 hi + lo
__global__ void k_split(void) {
    __shared__ float t[32][33];
    int which = blockIdx.z & 1;
    int i = blockIdx.z >> 1;
    int l0 = blockIdx.x * 32, c0 = blockIdx.y * 32;
    int tx = threadIdx.x, ty = threadIdx.y;
    const float* src = (which ? g_Fs : g_Bs) + (size_t)i * CH * L;
    for (int r = ty; r < 32; r += 8)
        t[r][tx] = src[(size_t)(c0 + r) * L + l0 + tx];
    __syncthreads();
    __nv_bfloat16* oh = (which ? g_Fh : g_Bh) + (size_t)i * L * CH;
    __nv_bfloat16* ol = (which ? g_Fl : g_Bl) + (size_t)i * L * CH;
    for (int r = ty; r < 32; r += 8) {
        float v = t[tx][r];                       // M[c0+tx][l0+r]
        __nv_bfloat16 h = __float2bfloat16(v);
        float lo = v - __bfloat162float(h);
        oh[(size_t)(l0 + r) * CH + c0 + tx] = h;
        ol[(size_t)(l0 + r) * CH + c0 + tx] = __float2bfloat16(lo);
    }
}

__global__ void k_bcl(const float* __restrict__ b) {
    int idx = blockIdx.x * blockDim.x + threadIdx.x;   // NB*CH*HH*WW
    int x = idx % WW;
    int t = idx / WW;
    int y = t % HH;
    int u = t / HH;
    int c = u % CH;
    int i = u / CH;
    g_bcl[((i * HH + y) * WW + x) * CH + c] = b[idx];
}

__global__ void k_sq(void) {
    int idx = blockIdx.x * blockDim.x + threadIdx.x;   // NB*L
    int i = idx / L, l = idx % L;
    const float* p = g_Bs + (size_t)i * CH * L + l;
    float s = 0.f;
#pragma unroll 8
    for (int c = 0; c < CH; ++c) { float v = p[(size_t)c * L]; s += v * v; }
    g_sq[idx] = s;
}

__global__ void k_norm(void) {
    int idx = blockIdx.x * blockDim.x + threadIdx.x;
    int i = idx / L, l = idx % L;
    int r = l / S, c = l % S;
    float s = 0.f;
    for (int dr = -1; dr <= 1; ++dr)
        for (int dc = -1; dc <= 1; ++dc) {
            int rr = r + dr, cc = c + dc;
            if ((unsigned)rr < S && (unsigned)cc < S) s += g_sq[i * L + rr * S + cc];
        }
    g_invn[idx] = rsqrtf(s + 0.1152f);
}

__global__ void k_mm(const float* __restrict__ mask) {
    int idx = blockIdx.x * blockDim.x + threadIdx.x;
    int i = idx / L, l = idx % L;
    int r = l / S, c = l % S;
    float s = 0.f;
    for (int dr = -1; dr <= 1; ++dr)
        for (int dc = -1; dc <= 1; ++dc) {
            int rr = r + dr, cc = c + dc;
            if ((unsigned)rr < S && (unsigned)cc < S)
                s += mask[i * HH * WW + (2 * rr) * WW + (2 * cc)];
        }
    g_mmv[idx] = (s * (1.0f / 9.0f) == 1.0f) ? 1.f : 0.f;
}

// ======== split-bf16 tensor GEMM: G = Bs^T * Fs  (hi*hi + hi*lo + lo*hi) ========
// smem tiles: 128 rows x 136 bf16 (272B stride -> conflict-free fragment loads)
#define TSTR 272
#define TILE_B (128 * TSTR)          // 34816 per tile
#define GSMEM  (4 * TILE_B)          // 139264

__device__ __forceinline__ void mma16816(float* d, const uint32_t* a, uint32_t b0, uint32_t b1) {
    asm volatile(
        "mma.sync.aligned.m16n8k16.row.col.f32.bf16.bf16.f32 "
        "{%0,%1,%2,%3}, {%4,%5,%6,%7}, {%8,%9}, {%0,%1,%2,%3};"
        : "+f"(d[0]), "+f"(d[1]), "+f"(d[2]), "+f"(d[3])
        : "r"(a[0]), "r"(a[1]), "r"(a[2]), "r"(a[3]), "r"(b0), "r"(b1));
}

__global__ __launch_bounds__(256) void k_gemm(void) {
    extern __shared__ char sm[];
    int i = blockIdx.z;
    int m0 = blockIdx.y * 128, n0 = blockIdx.x * 128;
    int tid = threadIdx.x, lane = tid & 31, wid = tid >> 5;
    int wm = wid >> 1, wn = wid & 1;     // 4 x 2 warps; warp tile 32(m) x 64(n)

    // one-shot load of 4 tiles (Ah, Al, Bh, Bl), each 128 rows x 256B
    {
        const __nv_bfloat16* srcs[4] = {
            g_Bh + ((size_t)i * L + m0) * CH,
            g_Bl + ((size_t)i * L + m0) * CH,
            g_Fh + ((size_t)i * L + n0) * CH,
            g_Fl + ((size_t)i * L + n0) * CH };
#pragma unroll
        for (int t4 = 0; t4 < 4; ++t4) {
            const uint4* s = (const uint4*)srcs[t4];
            char* d = sm + t4 * TILE_B;
#pragma unroll
            for (int q = tid; q < 2048; q += 256) {
                int r = q >> 4, c16 = q & 15;
                *(uint4*)(d + r * TSTR + c16 * 16) = s[q];
            }
        }
    }
    __syncthreads();

    float acc[2][8][4];
#pragma unroll
    for (int t = 0; t < 2; ++t)
#pragma unroll
        for (int u = 0; u < 8; ++u)
#pragma unroll
            for (int v = 0; v < 4; ++v) acc[t][u][v] = 0.f;

    const char* pAH = sm;
    const char* pAL = sm + TILE_B;
    const char* pBH = sm + 2 * TILE_B;
    const char* pBL = sm + 3 * TILE_B;

    for (int k0 = 0; k0 < 128; k0 += 16) {
        int kb = k0 * 2 + (lane & 3) * 4;
        uint32_t ah[2][4], al[2][4];
#pragma unroll
        for (int t = 0; t < 2; ++t) {
            int m = wm * 32 + t * 16 + (lane >> 2);
            ah[t][0] = *(const uint32_t*)(pAH + m * TSTR + kb);
            ah[t][1] = *(const uint32_t*)(pAH + (m + 8) * TSTR + kb);
            ah[t][2] = *(const uint32_t*)(pAH + m * TSTR + kb + 16);
            ah[t][3] = *(const uint32_t*)(pAH + (m + 8) * TSTR + kb + 16);
            al[t][0] = *(const uint32_t*)(pAL + m * TSTR + kb);
            al[t][1] = *(const uint32_t*)(pAL + (m + 8) * TSTR + kb);
            al[t][2] = *(const uint32_t*)(pAL + m * TSTR + kb + 16);
            al[t][3] = *(const uint32_t*)(pAL + (m + 8) * TSTR + kb + 16);
        }
#pragma unroll
        for (int u = 0; u < 8; ++u) {
            int n = wn * 64 + u * 8 + (lane >> 2);
            uint32_t bh0 = *(const uint32_t*)(pBH + n * TSTR + kb);
            uint32_t bh1 = *(const uint32_t*)(pBH + n * TSTR + kb + 16);
            uint32_t bl0 = *(const uint32_t*)(pBL + n * TSTR + kb);
            uint32_t bl1 = *(const uint32_t*)(pBL + n * TSTR + kb + 16);
#pragma unroll
            for (int t = 0; t < 2; ++t) {
                mma16816(acc[t][u], ah[t], bh0, bh1);
                mma16816(acc[t][u], ah[t], bl0, bl1);
                mma16816(acc[t][u], al[t], bh0, bh1);
            }
        }
    }

    // store D: per (t,u) tile, thread owns rows (lane/4, +8), cols (lane%4)*2..+1
    float* Cc = g_A + (size_t)i * LLn;
#pragma unroll
    for (int t = 0; t < 2; ++t) {
#pragma unroll
        for (int u = 0; u < 8; ++u) {
            float* base = Cc + (size_t)(m0 + wm * 32 + t * 16 + (lane >> 2)) * L
                          + n0 + wn * 64 + u * 8 + (lane & 3) * 2;
            *(float2*)base           = make_float2(acc[t][u][0], acc[t][u][1]);
            *(float2*)(base + 8 * L) = make_float2(acc[t][u][2], acc[t][u][3]);
        }
    }
}

// ================= stencil 1: 9-tap masked diagonal band of G, * invn[a] =================
__global__ __launch_bounds__(256) void k_corr(void) {
    int b = blockIdx.x * 256 + threadIdx.x;
    int ch = blockIdx.y, i = blockIdx.z;
    const float* src = g_A + (size_t)i * LLn;
    float* dst = g_B2 + (size_t)i * LLn;
    int r2 = b / S, c2 = b % S;
    for (int rr = 0; rr < 64; ++rr) {
        int a = ch * 64 + rr;
        int r1 = a / S, c1 = a % S;
        float s = 0.f;
#pragma unroll
        for (int dr = -1; dr <= 1; ++dr) {
            if ((unsigned)(r1 + dr) >= S || (unsigned)(r2 + dr) >= S) continue;
#pragma unroll
            for (int dc = -1; dc <= 1; ++dc) {
                if ((unsigned)(c1 + dc) >= S || (unsigned)(c2 + dc) >= S) continue;
                int off = dr * S + dc;
                s += src[(size_t)(a + off) * L + (b + off)];
            }
        }
        dst[(size_t)a * L + b] = s * g_invn[i * L + a];
    }
}

// ===== stencil 2: fused fuse_diag x2 + logit scale + per-chunk column max (materialized) =====
__global__ __launch_bounds__(256) void k_fuse(void) {
    int b = blockIdx.x * 256 + threadIdx.x;
    int ch = blockIdx.y, i = blockIdx.z;
    const float* src = g_B2 + (size_t)i * LLn;
    float* dst = g_A + (size_t)i * LLn;
    int bT = (b % S) * S + b / S;
    float pm = -1e30f;
    for (int rr = 0; rr < CR; ++rr) {
        int a = ch * CR + rr;
        int aT = (a % S) * S + a / S;
        float s = 0.f;
#pragma unroll
        for (int d2 = -1; d2 <= 1; ++d2) {
            int ta = aT + d2, tb = bT + d2;
            if ((unsigned)ta >= L || (unsigned)tb >= L) continue;
            int A2 = (ta % S) * S + ta / S;
            int B2 = (tb % S) * S + tb / S;
#pragma unroll
            for (int d1 = -1; d1 <= 1; ++d1) {
                int x = A2 + d1, y = B2 + d1;
                if ((unsigned)x >= L || (unsigned)y >= L) continue;
                s += src[(size_t)x * L + y];
            }
        }
        float lg = s * 10.0f * g_mmv[i * L + a];
        dst[(size_t)a * L + b] = lg;
        pm = fmaxf(pm, lg);
    }
    g_pmax[(i * CHK + ch) * L + b] = pm;
}

// ===== softmax: global max from pmax, chunk-skip, partial sums + candidates =====
__global__ void k_ext(void) {
    int b = blockIdx.x * 256 + threadIdx.x;
    int ch = blockIdx.y, i = blockIdx.z;
    float pmc = g_pmax[(i * CHK + ch) * L + b];
    float m = -1e30f;
#pragma unroll
    for (int c2 = 0; c2 < CHK; ++c2)
        m = fmaxf(m, g_pmax[(i * CHK + c2) * L + b]);
    if (pmc < m - 25.0f) {
        g_psum[(i * CHK + ch) * L + b] = 0.f;
        g_ccnt[(i * CHK + ch) * L + b] = 0;
        return;
    }
    const float* src = g_A + (size_t)i * LLn;
    float s = 0.f;
    int n = 0;
    size_t base = ((size_t)(i * L + b) * CHK + ch) * CR;
    for (int r = 0; r < CR; ++r) {
        int a = ch * CR + r;
        float d = src[(size_t)a * L + b] - m;
        if (d > -25.0f) {
            float e = __expf(d);
            s += e;
            if (g_mmv[i * L + a] > 0.5f) {
                g_lidx[base + n] = a;
                g_lw [base + n] = e;
                n++;
            }
        }
    }
    g_psum[(i * CHK + ch) * L + b] = s;
    g_ccnt[(i * CHK + ch) * L + b] = n;
}

// merge chunk lists -> dense list with normalized weights baked in
__global__ void k_comp(void) {
    int idx = blockIdx.x * 256 + threadIdx.x;   // NB*L
    int i = idx / L, b = idx % L;
    float s = 0.f;
#pragma unroll
    for (int ch = 0; ch < CHK; ++ch)
        s += g_psum[(i * CHK + ch) * L + b];
    float inv = 1.0f / s;
    int n = 0;
    size_t sbase = (size_t)(i * L + b) * CHK * CR;
    size_t dbase = (size_t)(i * L + b) * DCAP;
    for (int ch = 0; ch < CHK; ++ch) {
        int c = g_ccnt[(i * CHK + ch) * L + b];
        for (int j = 0; j < c; ++j) {
            if (n < DCAP) {
                g_didx[dbase + n] = g_lidx[sbase + ch * CR + j];
                g_dw [dbase + n] = g_lw [sbase + ch * CR + j] * inv;
            }
            n++;
        }
    }
    g_dn[idx] = n < DCAP ? n : DCAP;
}

// ================= sparse transposed-conv gather =================
__global__ __launch_bounds__(128) void k_out(float* __restrict__ out) {
    int p = blockIdx.x;            // 0..HH*WW-1
    int i = blockIdx.y;
    int c = threadIdx.x;
    int oy = p / WW, ox = p % WW;
    int ua = oy / 2 - 1 + (oy & 1);
    int va = ox / 2 - 1 + (ox & 1);
    float acc = 0.f;
    const float* bcl = g_bcl + (size_t)i * HH * WW * CH;
#pragma unroll
    for (int du = 0; du < 2; ++du) {
        int uu = ua + du;
        if ((unsigned)uu >= S) continue;
#pragma unroll
        for (int dv = 0; dv < 2; ++dv) {
            int vv = va + dv;
            if ((unsigned)vv >= S) continue;
            int bcol = uu * S + vv;
            int n = g_dn[i * L + bcol];
            size_t db = (size_t)(i * L + bcol) * DCAP;
            for (int j = 0; j < n; ++j) {
                int a   = g_didx[db + j];
                float w = g_dw [db + j];
                int r1 = a / S, c1 = a % S;
                int Y = oy + 2 * (r1 - uu);
                int X = ox + 2 * (c1 - vv);
                if ((unsigned)Y < HH && (unsigned)X < WW)
                    acc += w * bcl[((size_t)Y * WW + X) * CH + c];
            }
        }
    }
    out[((size_t)(i * CH + c) * HH + oy) * WW + ox] = acc * 0.25f;
}

extern "C" void kernel_launch(void* const* d_in, const int* in_sizes, int n_in,
                              void* d_out, int out_size) {
    (void)in_sizes; (void)n_in; (void)out_size;
    const float* b    = (const float*)d_in[0];
    const float* f    = (const float*)d_in[1];
    const float* mask = (const float*)d_in[2];
    float* out = (float*)d_out;

    cudaFuncSetAttribute(k_gemm, cudaFuncAttributeMaxDynamicSharedMemorySize, GSMEM);

    // gemm stays at slot 4 (ncu capture slot)
    k_sub<<<NB * CH * L / 256, 256>>>(b, f);          // 1
    {
        dim3 bs(32, 8);
        dim3 gs(L / 32, CH / 32, NB * 2);
        k_split<<<gs, bs>>>();                        // 2
    }
    k_sq<<<NB * L / 256, 256>>>();                    // 3
    {
        dim3 gg(L / 128, L / 128, NB);
        k_gemm<<<gg, 256, GSMEM>>>();                 // 4
    }
    k_norm<<<NB * L / 256, 256>>>();                  // 5
    {
        dim3 gs(L / 256, CHK, NB);
        k_corr<<<gs, 256>>>();                        // 6
    }
    k_mm<<<NB * L / 256, 256>>>(mask);                // 7
    k_bcl<<<NB * CH * HH * WW / 256, 256>>>(b);       // 8
    {
        dim3 gs(L / 256, CHK, NB);
        k_fuse<<<gs, 256>>>();                        // 9
        k_ext <<<gs, 256>>>();                        // 10
    }
    k_comp<<<NB * L / 256, 256>>>();                  // 11

    dim3 go(HH * WW, NB);
    k_out<<<go, 128>>>(out);                          // 12
}

// round 15
// speedup vs baseline: 1.2558x; 1.0274x over previous
#include <cuda_runtime.h>
#include <cuda_bf16.h>
#include <math.h>
#include <stdint.h>

#define NB 4
#define CH 128
#define HH 96
#define WW 96
#define S  48
#define L  2304
#define LLn 5308416   // L*L
#define CHK 36
#define CR  64
#define DCAP 128

// ---- scratch (static device globals; no allocation) ----
__device__ float g_A [(size_t)NB * LLn];
__device__ float g_B2[(size_t)NB * LLn];
__device__ float g_Bs[NB * CH * L];
__device__ float g_Fs[NB * CH * L];
__device__ __nv_bfloat16 g_Bh[(size_t)NB * L * CH];
__device__ __nv_bfloat16 g_Bl[(size_t)NB * L * CH];
__device__ __nv_bfloat16 g_Fh[(size_t)NB * L * CH];
__device__ __nv_bfloat16 g_Fl[(size_t)NB * L * CH];
__device__ float g_bcl[NB * HH * WW * CH];
__device__ float g_sq [NB * L];
__device__ float g_invn[NB * L];
__device__ float g_mmv[NB * L];
__device__ float g_pmax[NB * CHK * L];
__device__ float g_psum[NB * CHK * L];
__device__ int   g_ccnt[NB * CHK * L];
__device__ int   g_lidx[(size_t)NB * L * CHK * CR];
__device__ float g_lw  [(size_t)NB * L * CHK * CR];
__device__ int   g_dn  [NB * L];
__device__ int   g_didx[(size_t)NB * L * DCAP];
__device__ float g_dw  [(size_t)NB * L * DCAP];

// ================= prep kernels =================
__global__ void k_sub(const float* __restrict__ b, const float* __restrict__ f) {
    int idx = blockIdx.x * blockDim.x + threadIdx.x;   // NB*CH*L
    int l = idx % L;
    int t = idx / L;
    int c = t % CH;
    int i = t / CH;
    int r = l / S, cc = l % S;
    int src = ((i * CH + c) * HH + 2 * r) * WW + 2 * cc;
    g_Bs[idx] = b[src];
    g_Fs[idx] = f[src];
}

// transpose + bf16 hi/lo split: [i][c][l] f32 -> [i][l][c] bf16 hi + lo
__global__ void k_split(void) {
    __shared__ float t[32][33];
    int which = blockIdx.z & 1;
    int i = blockIdx.z >> 1;
    int l0 = blockIdx.x * 32, c0 = blockIdx.y * 32;
    int tx = threadIdx.x, ty = threadIdx.y;
    const float* src = (which ? g_Fs : g_Bs) + (size_t)i * CH * L;
    for (int r = ty; r < 32; r += 8)
        t[r][tx] = src[(size_t)(c0 + r) * L + l0 + tx];
    __syncthreads();
    __nv_bfloat16* oh = (which ? g_Fh : g_Bh) + (size_t)i * L * CH;
    __nv_bfloat16* ol = (which ? g_Fl : g_Bl) + (size_t)i * L * CH;
    for (int r = ty; r < 32; r += 8) {
        float v = t[tx][r];                       // M[c0+tx][l0+r]
        __nv_bfloat16 h = __float2bfloat16(v);
        float lo = v - __bfloat162float(h);
        oh[(size_t)(l0 + r) * CH + c0 + tx] = h;
        ol[(size_t)(l0 + r) * CH + c0 + tx] = __float2bfloat16(lo);
    }
}

__global__ void k_bcl(const float* __restrict__ b) {
    int idx = blockIdx.x * blockDim.x + threadIdx.x;   // NB*CH*HH*WW
    int x = idx % WW;
    int t = idx / WW;
    int y = t % HH;
    int u = t / HH;
    int c = u % CH;
    int i = u / CH;
    g_bcl[((i * HH + y) * WW + x) * CH + c] = b[idx];
}

__global__ void k_sq(void) {
    int idx = blockIdx.x * blockDim.x + threadIdx.x;   // NB*L
    int i = idx / L, l = idx % L;
    const float* p = g_Bs + (size_t)i * CH * L + l;
    float s = 0.f;
#pragma unroll 8
    for (int c = 0; c < CH; ++c) { float v = p[(size_t)c * L]; s += v * v; }
    g_sq[idx] = s;
}

__global__ void k_norm(void) {
    int idx = blockIdx.x * blockDim.x + threadIdx.x;
    int i = idx / L, l = idx % L;
    int r = l / S, c = l % S;
    float s = 0.f;
    for (int dr = -1; dr <= 1; ++dr)
        for (int dc = -1; dc <= 1; ++dc) {
            int rr = r + dr, cc = c + dc;
            if ((unsigned)rr < S && (unsigned)cc < S) s += g_sq[i * L + rr * S + cc];
        }
    g_invn[idx] = rsqrtf(s + 0.1152f);
}

__global__ void k_mm(const float* __restrict__ mask) {
    int idx = blockIdx.x * blockDim.x + threadIdx.x;
    int i = idx / L, l = idx % L;
    int r = l / S, c = l % S;
    float s = 0.f;
    for (int dr = -1; dr <= 1; ++dr)
        for (int dc = -1; dc <= 1; ++dc) {
            int rr = r + dr, cc = c + dc;
            if ((unsigned)rr < S && (unsigned)cc < S)
                s += mask[i * HH * WW + (2 * rr) * WW + (2 * cc)];
        }
    g_mmv[idx] = (s * (1.0f / 9.0f) == 1.0f) ? 1.f : 0.f;
}

// ======== split-bf16 tensor GEMM, K split in 2 halves for 2 CTA/SM occupancy ========
#define TSTR 144                      // 64 bf16 + 8 pad = 144B row stride
#define TILE_B (128 * TSTR)           // 18432 per tile-half
#define GSMEM  (4 * TILE_B)           // 73728

__device__ __forceinline__ void mma16816(float* d, const uint32_t* a, uint32_t b0, uint32_t b1) {
    asm volatile(
        "mma.sync.aligned.m16n8k16.row.col.f32.bf16.bf16.f32 "
        "{%0,%1,%2,%3}, {%4,%5,%6,%7}, {%8,%9}, {%0,%1,%2,%3};"
        : "+f"(d[0]), "+f"(d[1]), "+f"(d[2]), "+f"(d[3])
        : "r"(a[0]), "r"(a[1]), "r"(a[2]), "r"(a[3]), "r"(b0), "r"(b1));
}

__global__ __launch_bounds__(256, 2) void k_gemm(void) {
    extern __shared__ char sm[];
    int i = blockIdx.z;
    int m0 = blockIdx.y * 128, n0 = blockIdx.x * 128;
    int tid = threadIdx.x, lane = tid & 31, wid = tid >> 5;
    int wm = wid >> 1, wn = wid & 1;     // 4 x 2 warps; warp tile 32(m) x 64(n)

    float acc[2][8][4];
#pragma unroll
    for (int t = 0; t < 2; ++t)
#pragma unroll
        for (int u = 0; u < 8; ++u)
#pragma unroll
            for (int v = 0; v < 4; ++v) acc[t][u][v] = 0.f;

    const char* pAH = sm;
    const char* pAL = sm + TILE_B;
    const char* pBH = sm + 2 * TILE_B;
    const char* pBL = sm + 3 * TILE_B;

    for (int half = 0; half < 2; ++half) {
        // load 4 tile-halves (Ah, Al, Bh, Bl): 128 rows x 128B each
        {
            const __nv_bfloat16* srcs[4] = {
                g_Bh + ((size_t)i * L + m0) * CH,
                g_Bl + ((size_t)i * L + m0) * CH,
                g_Fh + ((size_t)i * L + n0) * CH,
                g_Fl + ((size_t)i * L + n0) * CH };
            if (half) __syncthreads();
#pragma unroll
            for (int t4 = 0; t4 < 4; ++t4) {
                const uint4* s = (const uint4*)srcs[t4];
                char* d = sm + t4 * TILE_B;
#pragma unroll
                for (int q = tid; q < 1024; q += 256) {
                    int r = q >> 3, c8 = q & 7;
                    *(uint4*)(d + r * TSTR + c8 * 16) = s[r * 16 + half * 8 + c8];
                }
            }
        }
        __syncthreads();

#pragma unroll
        for (int k0 = 0; k0 < 64; k0 += 16) {
            int kb = k0 * 2 + (lane & 3) * 4;
            uint32_t ah[2][4], al[2][4];
#pragma unroll
            for (int t = 0; t < 2; ++t) {
                int m = wm * 32 + t * 16 + (lane >> 2);
                ah[t][0] = *(const uint32_t*)(pAH + m * TSTR + kb);
                ah[t][1] = *(const uint32_t*)(pAH + (m + 8) * TSTR + kb);
                ah[t][2] = *(const uint32_t*)(pAH + m * TSTR + kb + 16);
                ah[t][3] = *(const uint32_t*)(pAH + (m + 8) * TSTR + kb + 16);
                al[t][0] = *(const uint32_t*)(pAL + m * TSTR + kb);
                al[t][1] = *(const uint32_t*)(pAL + (m + 8) * TSTR + kb);
                al[t][2] = *(const uint32_t*)(pAL + m * TSTR + kb + 16);
                al[t][3] = *(const uint32_t*)(pAL + (m + 8) * TSTR + kb + 16);
            }
#pragma unroll
            for (int u = 0; u < 8; ++u) {
                int n = wn * 64 + u * 8 + (lane >> 2);
                uint32_t bh0 = *(const uint32_t*)(pBH + n * TSTR + kb);
                uint32_t bh1 = *(const uint32_t*)(pBH + n * TSTR + kb + 16);
                uint32_t bl0 = *(const uint32_t*)(pBL + n * TSTR + kb);
                uint32_t bl1 = *(const uint32_t*)(pBL + n * TSTR + kb + 16);
#pragma unroll
                for (int t = 0; t < 2; ++t) {
                    mma16816(acc[t][u], ah[t], bh0, bh1);
                    mma16816(acc[t][u], ah[t], bl0, bl1);
                    mma16816(acc[t][u], al[t], bh0, bh1);
                }
            }
        }
    }

    float* Cc = g_A + (size_t)i * LLn;
#pragma unroll
    for (int t = 0; t < 2; ++t) {
#pragma unroll
        for (int u = 0; u < 8; ++u) {
            float* base = Cc + (size_t)(m0 + wm * 32 + t * 16 + (lane >> 2)) * L
                          + n0 + wn * 64 + u * 8 + (lane & 3) * 2;
            *(float2*)base           = make_float2(acc[t][u][0], acc[t][u][1]);
            *(float2*)(base + 8 * L) = make_float2(acc[t][u][2], acc[t][u][3]);
        }
    }
}

// ===== stencil 1: 9-tap masked diagonal band of G (RAW — invn deferred to k_fuse) =====
__global__ __launch_bounds__(256) void k_corr(void) {
    int b = blockIdx.x * 256 + threadIdx.x;
    int ch = blockIdx.y, i = blockIdx.z;
    const float* src = g_A + (size_t)i * LLn;
    float* dst = g_B2 + (size_t)i * LLn;
    int r2 = b / S, c2 = b % S;
    for (int rr = 0; rr < 64; ++rr) {
        int a = ch * 64 + rr;
        int r1 = a / S, c1 = a % S;
        float s = 0.f;
#pragma unroll
        for (int dr = -1; dr <= 1; ++dr) {
            if ((unsigned)(r1 + dr) >= S || (unsigned)(r2 + dr) >= S) continue;
#pragma unroll
            for (int dc = -1; dc <= 1; ++dc) {
                if ((unsigned)(c1 + dc) >= S || (unsigned)(c2 + dc) >= S) continue;
                int off = dr * S + dc;
                s += src[(size_t)(a + off) * L + (b + off)];
            }
        }
        dst[(size_t)a * L + b] = s;
    }
}

// ===== stencil 2: fuse_diag x2 (with invn[x] applied per tap) + logit scale + chunk max =====
__global__ __launch_bounds__(256) void k_fuse(void) {
    int b = blockIdx.x * 256 + threadIdx.x;
    int ch = blockIdx.y, i = blockIdx.z;
    const float* src = g_B2 + (size_t)i * LLn;
    const float* invn = g_invn + i * L;
    float* dst = g_A + (size_t)i * LLn;
    int bT = (b % S) * S + b / S;
    float pm = -1e30f;
    for (int rr = 0; rr < CR; ++rr) {
        int a = ch * CR + rr;
        int aT = (a % S) * S + a / S;
        float s = 0.f;
#pragma unroll
        for (int d2 = -1; d2 <= 1; ++d2) {
            int ta = aT + d2, tb = bT + d2;
            if ((unsigned)ta >= L || (unsigned)tb >= L) continue;
            int A2 = (ta % S) * S + ta / S;
            int B2 = (tb % S) * S + tb / S;
#pragma unroll
            for (int d1 = -1; d1 <= 1; ++d1) {
                int x = A2 + d1, y = B2 + d1;
                if ((unsigned)x >= L || (unsigned)y >= L) continue;
                s += src[(size_t)x * L + y] * invn[x];
            }
        }
        float lg = s * 10.0f * g_mmv[i * L + a];
        dst[(size_t)a * L + b] = lg;
        pm = fmaxf(pm, lg);
    }
    g_pmax[(i * CHK + ch) * L + b] = pm;
}

// ===== softmax: global max from pmax, chunk-skip, partial sums + candidates =====
__global__ void k_ext(void) {
    int b = blockIdx.x * 256 + threadIdx.x;
    int ch = blockIdx.y, i = blockIdx.z;
    float pmc = g_pmax[(i * CHK + ch) * L + b];
    float m = -1e30f;
#pragma unroll
    for (int c2 = 0; c2 < CHK; ++c2)
        m = fmaxf(m, g_pmax[(i * CHK + c2) * L + b]);
    if (pmc < m - 25.0f) {
        g_psum[(i * CHK + ch) * L + b] = 0.f;
        g_ccnt[(i * CHK + ch) * L + b] = 0;
        return;
    }
    const float* src = g_A + (size_t)i * LLn;
    float s = 0.f;
    int n = 0;
    size_t base = ((size_t)(i * L + b) * CHK + ch) * CR;
    for (int r = 0; r < CR; ++r) {
        int a = ch * CR + r;
        float d = src[(size_t)a * L + b] - m;
        if (d > -25.0f) {
            float e = __expf(d);
            s += e;
            if (g_mmv[i * L + a] > 0.5f) {
                g_lidx[base + n] = a;
                g_lw [base + n] = e;
                n++;
            }
        }
    }
    g_psum[(i * CHK + ch) * L + b] = s;
    g_ccnt[(i * CHK + ch) * L + b] = n;
}

// merge chunk lists -> dense list with normalized weights baked in
__global__ void k_comp(void) {
    int idx = blockIdx.x * 256 + threadIdx.x;   // NB*L
    int i = idx / L, b = idx % L;
    float s = 0.f;
#pragma unroll
    for (int ch = 0; ch < CHK; ++ch)
        s += g_psum[(i * CHK + ch) * L + b];
    float inv = 1.0f / s;
    int n = 0;
    size_t sbase = (size_t)(i * L + b) * CHK * CR;
    size_t dbase = (size_t)(i * L + b) * DCAP;
    for (int ch = 0; ch < CHK; ++ch) {
        int c = g_ccnt[(i * CHK + ch) * L + b];
        for (int j = 0; j < c; ++j) {
            if (n < DCAP) {
                g_didx[dbase + n] = g_lidx[sbase + ch * CR + j];
                g_dw [dbase + n] = g_lw [sbase + ch * CR + j] * inv;
            }
            n++;
        }
    }
    g_dn[idx] = n < DCAP ? n : DCAP;
}

// ================= sparse transposed-conv gather =================
__global__ __launch_bounds__(128) void k_out(float* __restrict__ out) {
    int p = blockIdx.x;            // 0..HH*WW-1
    int i = blockIdx.y;
    int c = threadIdx.x;
    int oy = p / WW, ox = p % WW;
    int ua = oy / 2 - 1 + (oy & 1);
    int va = ox / 2 - 1 + (ox & 1);
    float acc = 0.f;
    const float* bcl = g_bcl + (size_t)i * HH * WW * CH;
#pragma unroll
    for (int du = 0; du < 2; ++du) {
        int uu = ua + du;
        if ((unsigned)uu >= S) continue;
#pragma unroll
        for (int dv = 0; dv < 2; ++dv) {
            int vv = va + dv;
            if ((unsigned)vv >= S) continue;
            int bcol = uu * S + vv;
            int n = g_dn[i * L + bcol];
            size_t db = (size_t)(i * L + bcol) * DCAP;
            for (int j = 0; j < n; ++j) {
                int a   = g_didx[db + j];
                float w = g_dw [db + j];
                int r1 = a / S, c1 = a % S;
                int Y = oy + 2 * (r1 - uu);
                int X = ox + 2 * (c1 - vv);
                if ((unsigned)Y < HH && (unsigned)X < WW)
                    acc += w * bcl[((size_t)Y * WW + X) * CH + c];
            }
        }
    }
    out[((size_t)(i * CH + c) * HH + oy) * WW + ox] = acc * 0.25f;
}

extern "C" void kernel_launch(void* const* d_in, const int* in_sizes, int n_in,
                              void* d_out, int out_size) {
    (void)in_sizes; (void)n_in; (void)out_size;
    const float* b    = (const float*)d_in[0];
    const float* f    = (const float*)d_in[1];
    const float* mask = (const float*)d_in[2];
    float* out = (float*)d_out;

    cudaFuncSetAttribute(k_gemm, cudaFuncAttributeMaxDynamicSharedMemorySize, GSMEM);

    // slot 4 = k_corr (ncu capture slot); corr no longer needs invn
    k_sub<<<NB * CH * L / 256, 256>>>(b, f);          // 1
    {
        dim3 bs(32, 8);
        dim3 gs(L / 32, CH / 32, NB * 2);
        k_split<<<gs, bs>>>();                        // 2
    }
    {
        dim3 gg(L / 128, L / 128, NB);
        k_gemm<<<gg, 256, GSMEM>>>();                 // 3
    }
    {
        dim3 gs(L / 256, CHK, NB);
        k_corr<<<gs, 256>>>();                        // 4  <- profiled
    }
    k_sq<<<NB * L / 256, 256>>>();                    // 5
    k_norm<<<NB * L / 256, 256>>>();                  // 6
    k_mm<<<NB * L / 256, 256>>>(mask);                // 7
    k_bcl<<<NB * CH * HH * WW / 256, 256>>>(b);       // 8
    {
        dim3 gs(L / 256, CHK, NB);
        k_fuse<<<gs, 256>>>();                        // 9
        k_ext <<<gs, 256>>>();                        // 10
    }
    k_comp<<<NB * L / 256, 256>>>();                  // 11

    dim3 go(HH * WW, NB);
    k_out<<<go, 128>>>(out);                          // 12
}

// round 17
// speedup vs baseline: 1.2931x; 1.0297x over previous
#include <cuda_runtime.h>
#include <cuda_bf16.h>
#include <math.h>
#include <stdint.h>

#define NB 4
#define CH 128
#define HH 96
#define WW 96
#define S  48
#define L  2304
#define LLn 5308416   // L*L
#define CHK 36
#define CR  64
#define DCAP 128

// ---- scratch (static device globals; no allocation) ----
__device__ float g_A [(size_t)NB * LLn];
__device__ float g_B2[(size_t)NB * LLn];
__device__ float g_Bs[NB * CH * L];
__device__ float g_Fs[NB * CH * L];
__device__ __nv_bfloat16 g_Bh[(size_t)NB * L * CH];
__device__ __nv_bfloat16 g_Bl[(size_t)NB * L * CH];
__device__ __nv_bfloat16 g_Fh[(size_t)NB * L * CH];
__device__ __nv_bfloat16 g_Fl[(size_t)NB * L * CH];
__device__ float g_bcl[NB * HH * WW * CH];
__device__ float g_sq [NB * L];
__device__ float g_invn[NB * L];
__device__ float g_mmv[NB * L];
__device__ float g_pmax[NB * CHK * L];
__device__ float g_psum[NB * CHK * L];
__device__ int   g_ccnt[NB * CHK * L];
__device__ int   g_lidx[(size_t)NB * L * CHK * CR];
__device__ float g_lw  [(size_t)NB * L * CHK * CR];
__device__ int   g_dn  [NB * L];
__device__ int   g_didx[(size_t)NB * L * DCAP];
__device__ float g_dw  [(size_t)NB * L * DCAP];

// ================= prep kernels =================
__global__ void k_sub(const float* __restrict__ b, const float* __restrict__ f) {
    int idx = blockIdx.x * blockDim.x + threadIdx.x;   // NB*CH*L
    int l = idx % L;
    int t = idx / L;
    int c = t % CH;
    int i = t / CH;
    int r = l / S, cc = l % S;
    int src = ((i * CH + c) * HH + 2 * r) * WW + 2 * cc;
    g_Bs[idx] = b[src];
    g_Fs[idx] = f[src];
}

// transpose + bf16 hi/lo split: [i][c][l] f32 -> [i][l][c] bf16 hi + lo
__global__ void k_split(void) {
    __shared__ float t[32][33];
    int which = blockIdx.z & 1;
    int i = blockIdx.z >> 1;
    int l0 = blockIdx.x * 32, c0 = blockIdx.y * 32;
    int tx = threadIdx.x, ty = threadIdx.y;
    const float* src = (which ? g_Fs : g_Bs) + (size_t)i * CH * L;
    for (int r = ty; r < 32; r += 8)
        t[r][tx] = src[(size_t)(c0 + r) * L + l0 + tx];
    __syncthreads();
    __nv_bfloat16* oh = (which ? g_Fh : g_Bh) + (size_t)i * L * CH;
    __nv_bfloat16* ol = (which ? g_Fl : g_Bl) + (size_t)i * L * CH;
    for (int r = ty; r < 32; r += 8) {
        float v = t[tx][r];                       // M[c0+tx][l0+r]
        __nv_bfloat16 h = __float2bfloat16(v);
        float lo = v - __bfloat162float(h);
        oh[(size_t)(l0 + r) * CH + c0 + tx] = h;
        ol[(size_t)(l0 + r) * CH + c0 + tx] = __float2bfloat16(lo);
    }
}

__global__ void k_bcl(const float* __restrict__ b) {
    int idx = blockIdx.x * blockDim.x + threadIdx.x;   // NB*CH*HH*WW
    int x = idx % WW;
    int t = idx / WW;
    int y = t % HH;
    int u = t / HH;
    int c = u % CH;
    int i = u / CH;
    g_bcl[((i * HH + y) * WW + x) * CH + c] = b[idx];
}

__global__ void k_sq(void) {
    int idx = blockIdx.x * blockDim.x + threadIdx.x;   // NB*L
    int i = idx / L, l = idx % L;
    const float* p = g_Bs + (size_t)i * CH * L + l;
    float s = 0.f;
#pragma unroll 8
    for (int c = 0; c < CH; ++c) { float v = p[(size_t)c * L]; s += v * v; }
    g_sq[idx] = s;
}

__global__ void k_norm(void) {
    int idx = blockIdx.x * blockDim.x + threadIdx.x;
    int i = idx / L, l = idx % L;
    int r = l / S, c = l % S;
    float s = 0.f;
    for (int dr = -1; dr <= 1; ++dr)
        for (int dc = -1; dc <= 1; ++dc) {
            int rr = r + dr, cc = c + dc;
            if ((unsigned)rr < S && (unsigned)cc < S) s += g_sq[i * L + rr * S + cc];
        }
    g_invn[idx] = rsqrtf(s + 0.1152f);
}

__global__ void k_mm(const float* __restrict__ mask) {
    int idx = blockIdx.x * blockDim.x + threadIdx.x;
    int i = idx / L, l = idx % L;
    int r = l / S, c = l % S;
    float s = 0.f;
    for (int dr = -1; dr <= 1; ++dr)
        for (int dc = -1; dc <= 1; ++dc) {
            int rr = r + dr, cc = c + dc;
            if ((unsigned)rr < S && (unsigned)cc < S)
                s += mask[i * HH * WW + (2 * rr) * WW + (2 * cc)];
        }
    g_mmv[idx] = (s * (1.0f / 9.0f) == 1.0f) ? 1.f : 0.f;
}

// ======== split-bf16 tensor GEMM, K split in 2 halves for 2 CTA/SM occupancy ========
#define TSTR 144                      // 64 bf16 + 8 pad = 144B row stride
#define TILE_B (128 * TSTR)           // 18432 per tile-half
#define GSMEM  (4 * TILE_B)           // 73728

__device__ __forceinline__ void mma16816(float* d, const uint32_t* a, uint32_t b0, uint32_t b1) {
    asm volatile(
        "mma.sync.aligned.m16n8k16.row.col.f32.bf16.bf16.f32 "
        "{%0,%1,%2,%3}, {%4,%5,%6,%7}, {%8,%9}, {%0,%1,%2,%3};"
        : "+f"(d[0]), "+f"(d[1]), "+f"(d[2]), "+f"(d[3])
        : "r"(a[0]), "r"(a[1]), "r"(a[2]), "r"(a[3]), "r"(b0), "r"(b1));
}

__global__ __launch_bounds__(256, 2) void k_gemm(void) {
    extern __shared__ char sm[];
    int i = blockIdx.z;
    int m0 = blockIdx.y * 128, n0 = blockIdx.x * 128;
    int tid = threadIdx.x, lane = tid & 31, wid = tid >> 5;
    int wm = wid >> 1, wn = wid & 1;     // 4 x 2 warps; warp tile 32(m) x 64(n)

    float acc[2][8][4];
#pragma unroll
    for (int t = 0; t < 2; ++t)
#pragma unroll
        for (int u = 0; u < 8; ++u)
#pragma unroll
            for (int v = 0; v < 4; ++v) acc[t][u][v] = 0.f;

    const char* pAH = sm;
    const char* pAL = sm + TILE_B;
    const char* pBH = sm + 2 * TILE_B;
    const char* pBL = sm + 3 * TILE_B;

    for (int half = 0; half < 2; ++half) {
        {
            const __nv_bfloat16* srcs[4] = {
                g_Bh + ((size_t)i * L + m0) * CH,
                g_Bl + ((size_t)i * L + m0) * CH,
                g_Fh + ((size_t)i * L + n0) * CH,
                g_Fl + ((size_t)i * L + n0) * CH };
            if (half) __syncthreads();
#pragma unroll
            for (int t4 = 0; t4 < 4; ++t4) {
                const uint4* s = (const uint4*)srcs[t4];
                char* d = sm + t4 * TILE_B;
#pragma unroll
                for (int q = tid; q < 1024; q += 256) {
                    int r = q >> 3, c8 = q & 7;
                    *(uint4*)(d + r * TSTR + c8 * 16) = s[r * 16 + half * 8 + c8];
                }
            }
        }
        __syncthreads();

#pragma unroll
        for (int k0 = 0; k0 < 64; k0 += 16) {
            int kb = k0 * 2 + (lane & 3) * 4;
            uint32_t ah[2][4], al[2][4];
#pragma unroll
            for (int t = 0; t < 2; ++t) {
                int m = wm * 32 + t * 16 + (lane >> 2);
                ah[t][0] = *(const uint32_t*)(pAH + m * TSTR + kb);
                ah[t][1] = *(const uint32_t*)(pAH + (m + 8) * TSTR + kb);
                ah[t][2] = *(const uint32_t*)(pAH + m * TSTR + kb + 16);
                ah[t][3] = *(const uint32_t*)(pAH + (m + 8) * TSTR + kb + 16);
                al[t][0] = *(const uint32_t*)(pAL + m * TSTR + kb);
                al[t][1] = *(const uint32_t*)(pAL + (m + 8) * TSTR + kb);
                al[t][2] = *(const uint32_t*)(pAL + m * TSTR + kb + 16);
                al[t][3] = *(const uint32_t*)(pAL + (m + 8) * TSTR + kb + 16);
            }
#pragma unroll
            for (int u = 0; u < 8; ++u) {
                int n = wn * 64 + u * 8 + (lane >> 2);
                uint32_t bh0 = *(const uint32_t*)(pBH + n * TSTR + kb);
                uint32_t bh1 = *(const uint32_t*)(pBH + n * TSTR + kb + 16);
                uint32_t bl0 = *(const uint32_t*)(pBL + n * TSTR + kb);
                uint32_t bl1 = *(const uint32_t*)(pBL + n * TSTR + kb + 16);
#pragma unroll
                for (int t = 0; t < 2; ++t) {
                    mma16816(acc[t][u], ah[t], bh0, bh1);
                    mma16816(acc[t][u], ah[t], bl0, bl1);
                    mma16816(acc[t][u], al[t], bh0, bh1);
                }
            }
        }
    }

    float* Cc = g_A + (size_t)i * LLn;
#pragma unroll
    for (int t = 0; t < 2; ++t) {
#pragma unroll
        for (int u = 0; u < 8; ++u) {
            float* base = Cc + (size_t)(m0 + wm * 32 + t * 16 + (lane >> 2)) * L
                          + n0 + wn * 64 + u * 8 + (lane & 3) * 2;
            *(float2*)base           = make_float2(acc[t][u][0], acc[t][u][1]);
            *(float2*)(base + 8 * L) = make_float2(acc[t][u][2], acc[t][u][3]);
        }
    }
}

// diag-band constant offsets: off = dr*S + dc, pointer delta = off*(L+1)
__device__ __constant__ int c_off9[9]  = { -(S+1), -S, -(S-1), -1, 0, 1, S-1, S, S+1 };

// ===== stencil 1: 9-tap masked diagonal band of G (RAW; invn deferred) =====
// hoisted predicates + incremental (r1,c1) + rolling base, constant tap offsets
__global__ __launch_bounds__(256) void k_corr(void) {
    int b = blockIdx.x * 256 + threadIdx.x;
    int ch = blockIdx.y, i = blockIdx.z;
    const float* src = g_A + (size_t)i * LLn;
    float* dst = g_B2 + (size_t)i * LLn;
    int r2 = b / S, c2 = b % S;
    bool cOK[3], rOK2[3];
#pragma unroll
    for (int d = 0; d < 3; ++d) {
        cOK[d]  = (unsigned)(c2 + d - 1) < S;
        rOK2[d] = (unsigned)(r2 + d - 1) < S;
    }
    int a0 = ch * 64;
    int r1 = a0 / S, c1 = a0 % S;
    const float* base = src + (size_t)a0 * L + b;
    float* dp = dst + (size_t)a0 * L + b;
    for (int rr = 0; rr < 64; ++rr) {
        float s = 0.f;
#pragma unroll
        for (int dr = 0; dr < 3; ++dr) {
            bool rv = rOK2[dr] && (unsigned)(r1 + dr - 1) < S;
#pragma unroll
            for (int dc = 0; dc < 3; ++dc) {
                if (rv && cOK[dc] && (unsigned)(c1 + dc - 1) < S) {
                    int off = (dr - 1) * S + (dc - 1);
                    s += base[(ptrdiff_t)off * (L + 1)];
                }
            }
        }
        *dp = s;
        base += L; dp += L;
        if (++c1 == S) { c1 = 0; ++r1; }
    }
}

// ===== stencil 2: fuse_diag x2 (invn per tap) + logit scale + chunk max =====
// interior fast path: taps are the same diag band (off=d2*S+d1); boundary = exact general path
__global__ __launch_bounds__(256) void k_fuse(void) {
    int b = blockIdx.x * 256 + threadIdx.x;
    int ch = blockIdx.y, i = blockIdx.z;
    const float* src = g_B2 + (size_t)i * LLn;
    const float* invn = g_invn + i * L;
    const float* mmv = g_mmv + i * L;
    float* dst = g_A + (size_t)i * LLn;
    int r2 = b / S, c2 = b % S;
    bool bInt = (unsigned)(r2 - 1) < 46u && (unsigned)(c2 - 1) < 46u;
    int bT = c2 * S + r2;
    int a0 = ch * CR;
    int r1 = a0 / S, c1 = a0 % S;
    const float* base = src + (size_t)a0 * L + b;
    float* dp = dst + (size_t)a0 * L + b;
    float pm = -1e30f;
    for (int rr = 0; rr < CR; ++rr) {
        int a = a0 + rr;
        float s = 0.f;
        bool aInt = (unsigned)(r1 - 1) < 46u && (unsigned)(c1 - 1) < 46u;
        if (aInt && bInt) {
            const float* ivp = invn + a;
#pragma unroll
            for (int t = 0; t < 9; ++t) {
                int off = c_off9[t];
                s += base[(ptrdiff_t)off * (L + 1)] * ivp[off];
            }
        } else {
            int aT = c1 * S + r1;
#pragma unroll
            for (int d2 = -1; d2 <= 1; ++d2) {
                int ta = aT + d2, tb = bT + d2;
                if ((unsigned)ta >= L || (unsigned)tb >= L) continue;
                int A2 = (ta % S) * S + ta / S;
                int B2 = (tb % S) * S + tb / S;
#pragma unroll
                for (int d1 = -1; d1 <= 1; ++d1) {
                    int x = A2 + d1, y = B2 + d1;
                    if ((unsigned)x >= L || (unsigned)y >= L) continue;
                    s += src[(size_t)x * L + y] * invn[x];
                }
            }
        }
        float lg = s * 10.0f * mmv[a];
        *dp = lg;
        pm = fmaxf(pm, lg);
        base += L; dp += L;
        if (++c1 == S) { c1 = 0; ++r1; }
    }
    g_pmax[(i * CHK + ch) * L + b] = pm;
}

// ===== softmax: global max from pmax, chunk-skip, partial sums + candidates =====
__global__ void k_ext(void) {
    int b = blockIdx.x * 256 + threadIdx.x;
    int ch = blockIdx.y, i = blockIdx.z;
    float pmc = g_pmax[(i * CHK + ch) * L + b];
    float m = -1e30f;
#pragma unroll
    for (int c2 = 0; c2 < CHK; ++c2)
        m = fmaxf(m, g_pmax[(i * CHK + c2) * L + b]);
    if (pmc < m - 25.0f) {
        g_psum[(i * CHK + ch) * L + b] = 0.f;
        g_ccnt[(i * CHK + ch) * L + b] = 0;
        return;
    }
    const float* src = g_A + (size_t)i * LLn;
    float s = 0.f;
    int n = 0;
    size_t base = ((size_t)(i * L + b) * CHK + ch) * CR;
    for (int r = 0; r < CR; ++r) {
        int a = ch * CR + r;
        float d = src[(size_t)a * L + b] - m;
        if (d > -25.0f) {
            float e = __expf(d);
            s += e;
            if (g_mmv[i * L + a] > 0.5f) {
                g_lidx[base + n] = a;
                g_lw [base + n] = e;
                n++;
            }
        }
    }
    g_psum[(i * CHK + ch) * L + b] = s;
    g_ccnt[(i * CHK + ch) * L + b] = n;
}

// merge chunk lists -> dense list with normalized weights baked in
__global__ void k_comp(void) {
    int idx = blockIdx.x * 256 + threadIdx.x;   // NB*L
    int i = idx / L, b = idx % L;
    float s = 0.f;
#pragma unroll
    for (int ch = 0; ch < CHK; ++ch)
        s += g_psum[(i * CHK + ch) * L + b];
    float inv = 1.0f / s;
    int n = 0;
    size_t sbase = (size_t)(i * L + b) * CHK * CR;
    size_t dbase = (size_t)(i * L + b) * DCAP;
    for (int ch = 0; ch < CHK; ++ch) {
        int c = g_ccnt[(i * CHK + ch) * L + b];
        for (int j = 0; j < c; ++j) {
            if (n < DCAP) {
                g_didx[dbase + n] = g_lidx[sbase + ch * CR + j];
                g_dw [dbase + n] = g_lw [sbase + ch * CR + j] * inv;
            }
            n++;
        }
    }
    g_dn[idx] = n < DCAP ? n : DCAP;
}

// ================= sparse transposed-conv gather =================
__global__ __launch_bounds__(128) void k_out(float* __restrict__ out) {
    int p = blockIdx.x;            // 0..HH*WW-1
    int i = blockIdx.y;
    int c = threadIdx.x;
    int oy = p / WW, ox = p % WW;
    int ua = oy / 2 - 1 + (oy & 1);
    int va = ox / 2 - 1 + (ox & 1);
    float acc = 0.f;
    const float* bcl = g_bcl + (size_t)i * HH * WW * CH;
#pragma unroll
    for (int du = 0; du < 2; ++du) {
        int uu = ua + du;
        if ((unsigned)uu >= S) continue;
#pragma unroll
        for (int dv = 0; dv < 2; ++dv) {
            int vv = va + dv;
            if ((unsigned)vv >= S) continue;
            int bcol = uu * S + vv;
            int n = g_dn[i * L + bcol];
            size_t db = (size_t)(i * L + bcol) * DCAP;
            for (int j = 0; j < n; ++j) {
                int a   = g_didx[db + j];
                float w = g_dw [db + j];
                int r1 = a / S, c1 = a % S;
                int Y = oy + 2 * (r1 - uu);
                int X = ox + 2 * (c1 - vv);
                if ((unsigned)Y < HH && (unsigned)X < WW)
                    acc += w * bcl[((size_t)Y * WW + X) * CH + c];
            }
        }
    }
    out[((size_t)(i * CH + c) * HH + oy) * WW + ox] = acc * 0.25f;
}

extern "C" void kernel_launch(void* const* d_in, const int* in_sizes, int n_in,
                              void* d_out, int out_size) {
    (void)in_sizes; (void)n_in; (void)out_size;
    const float* b    = (const float*)d_in[0];
    const float* f    = (const float*)d_in[1];
    const float* mask = (const float*)d_in[2];
    float* out = (float*)d_out;

    cudaFuncSetAttribute(k_gemm, cudaFuncAttributeMaxDynamicSharedMemorySize, GSMEM);

    // slot 4 = k_corr (ncu capture slot)
    k_sub<<<NB * CH * L / 256, 256>>>(b, f);          // 1
    {
        dim3 bs(32, 8);
        dim3 gs(L / 32, CH / 32, NB * 2);
        k_split<<<gs, bs>>>();                        // 2
    }
    {
        dim3 gg(L / 128, L / 128, NB);
        k_gemm<<<gg, 256, GSMEM>>>();                 // 3
    }
    {
        dim3 gs(L / 256, CHK, NB);
        k_corr<<<gs, 256>>>();                        // 4  <- profiled
    }
    k_sq<<<NB * L / 256, 256>>>();                    // 5
    k_norm<<<NB * L / 256, 256>>>();                  // 6
    k_mm<<<NB * L / 256, 256>>>(mask);                // 7
    k_bcl<<<NB * CH * HH * WW / 256, 256>>>(b);       // 8
    {
        dim3 gs(L / 256, CHK, NB);
        k_fuse<<<gs, 256>>>();                        // 9
        k_ext <<<gs, 256>>>();                        // 10
    }
    k_comp<<<NB * L / 256, 256>>>();                  // 11

    dim3 go(HH * WW, NB);
    k_out<<<go, 128>>>(out);                          // 12
}